// round 9
// baseline (speedup 1.0000x reference)
#include <cuda_runtime.h>
#include <cstdint>

// Problem constants
#define B_   8
#define K_   65536
#define C_   128
#define N_   1024
#define CPB  16               // CTAs per batch (grid = 128 = one wave, co-resident)
#define PTSc (K_/CPB)         // 4096 points per CTA
#define TPB  512
#define PPT  (PTSc/TPB)       // 8 points per thread
#define NW   (TPB/32)         // 16 warps

// Output layout: [ new_xyz (B,N,3) | new_features (B,C,N) | sample_inds (B,N) ], float32
#define OXYZ  0
#define OFEAT (B_*N_*3)
#define OIND  (OFEAT + B_*C_*N_)

__device__ int g_inds[B_*N_];
__device__ unsigned g_epoch;                   // bumped once per launch (graph-replay-safe tags)
__device__ uint4 g_slots[B_][2][CPB][2];       // [batch][buf][rank][half], 16B packets

static __device__ __forceinline__ void stv4(uint4* p, uint32_t a, uint32_t b,
                                            uint32_t c, uint32_t d){
  asm volatile("st.volatile.global.v4.u32 [%0], {%1,%2,%3,%4};"
               :: "l"(p), "r"(a), "r"(b), "r"(c), "r"(d) : "memory");
}
static __device__ __forceinline__ uint4 ldv4(const uint4* p){
  uint4 v;
  asm volatile("ld.volatile.global.v4.u32 {%0,%1,%2,%3}, [%4];"
               : "=r"(v.x), "=r"(v.y), "=r"(v.z), "=r"(v.w) : "l"(p) : "memory");
  return v;
}

// Warp-wide (dist,idx) argmax via two REDUX ops; min index wins ties (jnp.argmax).
static __device__ __forceinline__ void warp_argmax(uint32_t dbits, uint32_t idx,
                                                   uint32_t& out_d, uint32_t& out_i){
  uint32_t wmax = __reduce_max_sync(0xffffffffu, dbits);
  uint32_t cand = (dbits == wmax) ? idx : 0xffffffffu;
  out_i = __reduce_min_sync(0xffffffffu, cand);
  out_d = wmax;
}

// 16 CTAs per batch, plain grid (no clusters). Per iteration:
//  1) register-resident distance update (exact unfused (dx^2+dy^2)+dz^2) + argmax
//  2) REDUX warp argmax -> smem; __syncthreads
//  3) warp0: REDUX over 16 warp candidates; lane0 posts two tag-validated 16B
//     packets {tag,dist,idx,x} {tag,y,z,-} to this CTA's L2 slot (volatile v4)
//  4) ALL warps: poll the batch's 16 slots (lane i -> slot i), REDUX-argmax,
//     shfl winner coords from owning lane. Double-buffered; epoch-tagged.
__global__ void __launch_bounds__(TPB,1)
fps_kernel(const float* __restrict__ xyz, float* __restrict__ out)
{
  extern __shared__ float spts[];               // 3*PTSc floats = 48KB (idx->coords)
  __shared__ uint32_t wd[NW], wi[NW];

  const int tid  = threadIdx.x;
  const int lane = tid & 31;
  const int w    = tid >> 5;
  const int b    = blockIdx.x >> 4;             // batch
  const int rank = blockIdx.x & (CPB-1);        // CTA within batch
  const float* xb = xyz + (size_t)b * K_ * 3;
  const int pbase = rank * PTSc;
  const unsigned epoch = g_epoch;               // constant for this launch

  if (rank == 0 && tid == 0){
    size_t o = (size_t)b * N_;
    out[OXYZ + o*3 + 0] = xb[0];
    out[OXYZ + o*3 + 1] = xb[1];
    out[OXYZ + o*3 + 2] = xb[2];
    out[OIND + o] = 0.0f;
    g_inds[o] = 0;
  }

  // smem copy of this CTA's points (coalesced) for O(1) idx->coords lookup
  for (int i = tid; i < 3*PTSc; i += TPB) spts[i] = xb[pbase*3 + i];

  // register-resident points + running distances
  float px[PPT], py[PPT], pz[PPT], dist[PPT];
#pragma unroll
  for (int j = 0; j < PPT; j++){
    int p = pbase + j*TPB + tid;
    px[j] = xb[3*p + 0];
    py[j] = xb[3*p + 1];
    pz[j] = xb[3*p + 2];
    dist[j] = 1e10f;
  }
  float cx = xb[0], cy = xb[1], cz = xb[2];     // first pick = index 0
  __syncthreads();

  uint4* slot0 = &g_slots[b][0][rank][0];       // this CTA's packets (buf 0)
  const uint4* pslot = &g_slots[b][0][lane & (CPB-1)][0];   // polled slot (buf 0)

  for (int t = 1; t < N_; t++){
    const uint32_t buf = (uint32_t)(t & 1);
    const uint32_t tag = (epoch << 11) | (uint32_t)t;       // unique across replays

    // ---- 1) distance update (exact: unfused rn mul/add, matches reference) ----
#pragma unroll
    for (int j = 0; j < PPT; j++){
      float dx = px[j] - cx, dy = py[j] - cy, dz = pz[j] - cz;
      float d = __fadd_rn(__fadd_rn(__fmul_rn(dx,dx), __fmul_rn(dy,dy)),
                          __fmul_rn(dz,dz));
      dist[j] = fminf(dist[j], d);
    }
    // per-thread max (pairwise tree) + descending eq-scan (lowest idx on tie)
    float m01 = fmaxf(dist[0], dist[1]), m23 = fmaxf(dist[2], dist[3]);
    float m45 = fmaxf(dist[4], dist[5]), m67 = fmaxf(dist[6], dist[7]);
    const float m = fmaxf(fmaxf(m01, m23), fmaxf(m45, m67));
    int loc = 0;
#pragma unroll
    for (int j = PPT-1; j >= 0; j--) if (dist[j] == m) loc = j*TPB + tid;

    // ---- 2) warp argmax via REDUX ----
    uint32_t wD, wI;
    warp_argmax(__float_as_uint(m), (uint32_t)(pbase + loc), wD, wI);
    if (lane == 0){ wd[w] = wD; wi[w] = wI; }
    __syncthreads();

    // ---- 3) warp0: CTA reduce + post packets to L2 ----
    if (w == 0){
      uint32_t cD, cI;
      warp_argmax(wd[lane & (NW-1)], wi[lane & (NW-1)], cD, cI);
      if (lane == 0){
        int lcl = (int)cI - pbase;
        uint32_t X = __float_as_uint(spts[3*lcl + 0]);
        uint32_t Y = __float_as_uint(spts[3*lcl + 1]);
        uint32_t Z = __float_as_uint(spts[3*lcl + 2]);
        uint4* s = slot0 + buf * (CPB*2);
        stv4(s + 0, tag, cD, cI, X);
        stv4(s + 1, tag, Y, Z, 0u);
      }
    }

    // ---- 4) all warps: poll 16 slots, reduce, pick winner ----
    uint4 h0, h1;
    bool need = (lane < CPB);
    bool r0 = !need, r1 = !need;
    const uint4* ps = pslot + buf * (CPB*2);
    do {
      if (!r0){ h0 = ldv4(ps + 0); r0 = (h0.x == tag); }
      if (!r1){ h1 = ldv4(ps + 1); r1 = (h1.x == tag); }
    } while (__any_sync(0xffffffffu, !(r0 && r1)));

    uint32_t db = need ? h0.y : 0u;
    uint32_t ix = need ? h0.z : 0xffffffffu;
    uint32_t gD, gI;
    warp_argmax(db, ix, gD, gI);
    const int s = (int)(gI >> 12);              // owning rank (PTSc = 4096)
    cx = __uint_as_float(__shfl_sync(0xffffffffu, h0.w, s));
    cy = __uint_as_float(__shfl_sync(0xffffffffu, h1.y, s));
    cz = __uint_as_float(__shfl_sync(0xffffffffu, h1.z, s));

    if (rank == 0 && tid == 0){                 // off the serial chain
      size_t o = (size_t)b * N_ + t;
      out[OXYZ + o*3 + 0] = cx;
      out[OXYZ + o*3 + 1] = cy;
      out[OXYZ + o*3 + 2] = cz;
      out[OIND + o] = (float)gI;
      g_inds[o] = (int)gI;
    }
  }
}

// Feature gather: out[b][c][t] = feat[b][c][ inds[b][t] ]
__global__ void gather_kernel(const float* __restrict__ feat, float* __restrict__ out)
{
  int i = blockIdx.x * blockDim.x + threadIdx.x;   // b*C*N + c*N + t
  int t  = i & (N_ - 1);
  int bc = i >> 10;            // b*C + c
  int bb = bc >> 7;            // / C_
  int idx = g_inds[bb * N_ + t];
  out[OFEAT + i] = feat[(size_t)bc * K_ + idx];
}

// Bump the epoch so slot tags never collide across graph replays.
__global__ void bump_epoch_kernel(){ g_epoch = g_epoch + 1u; }

extern "C" void kernel_launch(void* const* d_in, const int* in_sizes, int n_in,
                              void* d_out, int out_size)
{
  const float* xyz  = (const float*)d_in[0];   // (B,K,3)
  const float* feat = (const float*)d_in[1];   // (B,C,K)
  float* out = (float*)d_out;

  static int smem_set = 0;
  if (!smem_set){
    cudaFuncSetAttribute(fps_kernel, cudaFuncAttributeMaxDynamicSharedMemorySize,
                         3*PTSc*(int)sizeof(float));
    smem_set = 1;
  }

  bump_epoch_kernel<<<1,1>>>();
  fps_kernel<<<B_ * CPB, TPB, 3*PTSc*sizeof(float)>>>(xyz, out);
  gather_kernel<<<(B_ * C_ * N_) / 256, 256>>>(feat, out);
}

// round 10
// speedup vs baseline: 2.6175x; 2.6175x over previous
#include <cuda_runtime.h>
#include <cstdint>

// Problem constants
#define B_  8
#define K_  65536
#define C_  128
#define N_  1024
#define CL  8                 // CTAs (cluster) per batch
#define PTS (K_/CL)           // 8192 points per CTA
#define TPB 512
#define PPT (PTS/TPB)         // 16 points per thread
#define NW  (TPB/32)          // 16 warps

// Output layout: [ new_xyz (B,N,3) | new_features (B,C,N) | sample_inds (B,N) ], float32
#define OXYZ  0
#define OFEAT (B_*N_*3)
#define OIND  (OFEAT + B_*C_*N_)

__device__ int g_inds[B_*N_];
__device__ unsigned g_epoch;     // bumped once per launch: graph-replay-safe tags

static __device__ __forceinline__ uint32_t cvta_s(const void* p){
  return (uint32_t)__cvta_generic_to_shared(p);
}
static __device__ __forceinline__ uint32_t mapa_rank(uint32_t a, uint32_t r){
  uint32_t o; asm("mapa.shared::cluster.u32 %0, %1, %2;" : "=r"(o) : "r"(a), "r"(r)); return o;
}
static __device__ __forceinline__ void st_cl_v4(uint32_t a, uint32_t x0, uint32_t x1,
                                                uint32_t x2, uint32_t x3){
  asm volatile("st.shared::cluster.v4.b32 [%0], {%1,%2,%3,%4};"
               :: "r"(a), "r"(x0), "r"(x1), "r"(x2), "r"(x3) : "memory");
}
static __device__ __forceinline__ uint4 ld_s_v4_vol(uint32_t a){
  uint4 v;
  asm volatile("ld.volatile.shared.v4.u32 {%0,%1,%2,%3}, [%4];"
               : "=r"(v.x), "=r"(v.y), "=r"(v.z), "=r"(v.w) : "r"(a) : "memory");
  return v;
}
static __device__ __forceinline__ void cluster_sync_(){
  asm volatile("barrier.cluster.arrive.aligned;" ::: "memory");
  asm volatile("barrier.cluster.wait.aligned;" ::: "memory");
}

// Warp-wide (dist,idx) argmax via two REDUX ops; min index wins ties (jnp.argmax).
static __device__ __forceinline__ void warp_argmax(uint32_t dbits, uint32_t idx,
                                                   uint32_t& out_d, uint32_t& out_i){
  uint32_t wmax = __reduce_max_sync(0xffffffffu, dbits);
  uint32_t cand = (dbits == wmax) ? idx : 0xffffffffu;
  out_i = __reduce_min_sync(0xffffffffu, cand);
  out_d = wmax;
}

// One 8-CTA cluster per batch. Points + running min-dist register-resident.
// Per iteration:
//  1) scalar distance update (exact unfused (dx^2+dy^2)+dz^2) + per-thread argmax
//  2) REDUX warp argmax -> smem; __syncthreads
//  3) warp0: REDUX over 16 warp candidates; lanes 0..7 ship two tag-validated
//     16B packets {tag,dist,idx,x} {tag,y,z,0} to every CTA's slot
//     (st.shared::cluster.v4 — NO mbarrier, no arrive, no release stall)
//  4) ALL warps spin on local smem tags (volatile LDS), REDUX the 8 slots,
//     shfl winner coords from owning lane. Double-buffered; epoch-tagged.
__global__ void __launch_bounds__(TPB,1) __cluster_dims__(CL,1,1)
fps_kernel(const float* __restrict__ xyz, float* __restrict__ out)
{
  extern __shared__ float spts[];               // 3*PTS floats = 96KB (idx->coords)
  __shared__ uint32_t wd[NW], wi[NW];           // per-warp candidates
  __shared__ uint4 slots[2][CL][2];             // [buf][src_rank][half] 16B packets

  const int tid  = threadIdx.x;
  const int lane = tid & 31;
  const int w    = tid >> 5;
  const int b    = blockIdx.x / CL;
  const int rank = blockIdx.x % CL;
  const float* xb = xyz + (size_t)b * K_ * 3;
  const int pbase = rank * PTS;
  const unsigned epoch = g_epoch;               // constant per launch

  if (rank == 0 && tid == 0){
    size_t o = (size_t)b * N_;
    out[OXYZ + o*3 + 0] = xb[0];
    out[OXYZ + o*3 + 1] = xb[1];
    out[OXYZ + o*3 + 2] = xb[2];
    out[OIND + o] = 0.0f;
    g_inds[o] = 0;
  }
  // invalidate slot tags (never matches any (epoch<<11)|t)
  if (tid < 2*CL*2) ((uint4*)slots)[tid] = make_uint4(0xffffffffu,0,0,0);

  // smem copy of this CTA's points (coalesced) for O(1) idx->coords lookup
  for (int i = tid; i < 3*PTS; i += TPB) spts[i] = xb[pbase*3 + i];

  // register-resident points + running distances
  float px[PPT], py[PPT], pz[PPT], dist[PPT];
#pragma unroll
  for (int j = 0; j < PPT; j++){
    int p = pbase + j*TPB + tid;
    px[j] = xb[3*p + 0];
    py[j] = xb[3*p + 1];
    pz[j] = xb[3*p + 2];
    dist[j] = 1e10f;
  }
  float cx = xb[0], cy = xb[1], cz = xb[2];     // first pick = index 0

  __syncthreads();
  cluster_sync_();   // slot-tag init visible cluster-wide before any remote store

  // warp0 lanes 0..7: remote packet addresses in CTA `lane` (buf 0)
  uint32_t r_slot = 0;
  if (w == 0 && lane < CL)
    r_slot = mapa_rank(cvta_s(&slots[0][rank][0]), (uint32_t)lane);
  const uint32_t l_slot = cvta_s(&slots[0][0][0]) + (uint32_t)(lane & (CL-1)) * 32;

  for (int t = 1; t < N_; t++){
    const uint32_t buf = (uint32_t)(t & 1);
    const uint32_t tag = (epoch << 11) | (uint32_t)t;

    // ---- 1) distance update (exact: unfused rn mul/add, matches reference) ----
#pragma unroll
    for (int j = 0; j < PPT; j++){
      float dx = px[j] - cx, dy = py[j] - cy, dz = pz[j] - cz;
      float d = __fadd_rn(__fadd_rn(__fmul_rn(dx,dx), __fmul_rn(dy,dy)),
                          __fmul_rn(dz,dz));
      dist[j] = fminf(dist[j], d);
    }
    // per-thread max (pairwise tree) + descending eq-scan (lowest idx on tie)
    float m01 = fmaxf(dist[0], dist[1]),   m23 = fmaxf(dist[2], dist[3]);
    float m45 = fmaxf(dist[4], dist[5]),   m67 = fmaxf(dist[6], dist[7]);
    float m89 = fmaxf(dist[8], dist[9]),   mab = fmaxf(dist[10], dist[11]);
    float mcd = fmaxf(dist[12], dist[13]), mef = fmaxf(dist[14], dist[15]);
    float q0 = fmaxf(m01, m23), q1 = fmaxf(m45, m67);
    float q2 = fmaxf(m89, mab), q3 = fmaxf(mcd, mef);
    const float m = fmaxf(fmaxf(q0, q1), fmaxf(q2, q3));
    int loc = 0;
#pragma unroll
    for (int j = PPT-1; j >= 0; j--) if (dist[j] == m) loc = j*TPB + tid;

    // ---- 2) warp argmax via REDUX ----
    uint32_t wD, wI;
    warp_argmax(__float_as_uint(m), (uint32_t)(pbase + loc), wD, wI);
    if (lane == 0){ wd[w] = wD; wi[w] = wI; }
    __syncthreads();

    // ---- 3) warp0: CTA reduce + all-to-all packet ship (no barrier ops) ----
    if (w == 0){
      uint32_t cD, cI;
      warp_argmax(wd[lane & (NW-1)], wi[lane & (NW-1)], cD, cI);
      int lcl = (int)cI - pbase;                // CTA winner, local offset
      if (lane < CL){
        uint32_t X = __float_as_uint(spts[3*lcl + 0]);
        uint32_t Y = __float_as_uint(spts[3*lcl + 1]);
        uint32_t Z = __float_as_uint(spts[3*lcl + 2]);
        uint32_t a = r_slot + buf * (uint32_t)(CL * 32);
        st_cl_v4(a,      tag, cD, cI, X);
        st_cl_v4(a + 16, tag, Y,  Z,  0u);
      }
    }

    // ---- 4) all warps: spin on local tags, reduce 8 slots, pick winner ----
    const uint32_t pa = l_slot + buf * (uint32_t)(CL * 32);
    uint4 h0, h1;
    bool need = (lane < CL);
    bool r0 = !need, r1 = !need;
    do {
      if (!r0){ h0 = ld_s_v4_vol(pa);      r0 = (h0.x == tag); }
      if (!r1){ h1 = ld_s_v4_vol(pa + 16); r1 = (h1.x == tag); }
    } while (__any_sync(0xffffffffu, !(r0 && r1)));

    uint32_t db = need ? h0.y : 0u;
    uint32_t ix = need ? h0.z : 0xffffffffu;
    uint32_t gD, gI;
    warp_argmax(db, ix, gD, gI);
    const int s = (int)(gI >> 13);              // owning rank (PTS = 8192)
    cx = __uint_as_float(__shfl_sync(0xffffffffu, h0.w, s));
    cy = __uint_as_float(__shfl_sync(0xffffffffu, h1.y, s));
    cz = __uint_as_float(__shfl_sync(0xffffffffu, h1.z, s));

    if (rank == 0 && tid == 0){                 // off the serial chain
      size_t o = (size_t)b * N_ + t;
      out[OXYZ + o*3 + 0] = cx;
      out[OXYZ + o*3 + 1] = cy;
      out[OXYZ + o*3 + 2] = cz;
      out[OIND + o] = (float)gI;
      g_inds[o] = (int)gI;
    }
  }
  cluster_sync_();   // no CTA exits with remote stores possibly in flight
}

// Feature gather: out[b][c][t] = feat[b][c][ inds[b][t] ]
__global__ void gather_kernel(const float* __restrict__ feat, float* __restrict__ out)
{
  int i = blockIdx.x * blockDim.x + threadIdx.x;   // b*C*N + c*N + t
  int t  = i & (N_ - 1);
  int bc = i >> 10;            // b*C + c
  int bb = bc >> 7;            // / C_
  int idx = g_inds[bb * N_ + t];
  out[OFEAT + i] = feat[(size_t)bc * K_ + idx];
}

// Bump the epoch so packet tags never collide across graph replays.
__global__ void bump_epoch_kernel(){ g_epoch = g_epoch + 1u; }

extern "C" void kernel_launch(void* const* d_in, const int* in_sizes, int n_in,
                              void* d_out, int out_size)
{
  const float* xyz  = (const float*)d_in[0];   // (B,K,3)
  const float* feat = (const float*)d_in[1];   // (B,C,K)
  float* out = (float*)d_out;

  static int smem_set = 0;
  if (!smem_set){
    cudaFuncSetAttribute(fps_kernel, cudaFuncAttributeMaxDynamicSharedMemorySize,
                         3*PTS*(int)sizeof(float));
    smem_set = 1;
  }

  bump_epoch_kernel<<<1,1>>>();
  fps_kernel<<<B_ * CL, TPB, 3*PTS*sizeof(float)>>>(xyz, out);
  gather_kernel<<<(B_ * C_ * N_) / 256, 256>>>(feat, out);
}